// round 11
// baseline (speedup 1.0000x reference)
#include <cuda_runtime.h>
#include <cuda_bf16.h>
#include <cstdint>

typedef unsigned long long u64;

__device__ __forceinline__ u64 pk2(float lo, float hi) {
    u64 d; asm("mov.b64 %0, {%1, %2};" : "=l"(d) : "f"(lo), "f"(hi)); return d;
}
__device__ __forceinline__ void upk2(u64 v, float& lo, float& hi) {
    asm("mov.b64 {%0, %1}, %2;" : "=f"(lo), "=f"(hi) : "l"(v));
}
__device__ __forceinline__ u64 fma2(u64 a, u64 b, u64 c) {
    u64 d; asm("fma.rn.f32x2 %0, %1, %2, %3;" : "=l"(d) : "l"(a), "l"(b), "l"(c)); return d;
}

__device__ __forceinline__ int q_of(float t) {
    // t*1024 is exact in fp32 (power-of-two scale), so truncation == floor,
    // matching the reference's interval comparisons bit-exactly.
    int q = (int)(t * 1024.0f);
    q = q < 0 ? 0 : (q > 1023 ? 1023 : q);
    return q;
}

// Fused, 512 threads/block, 128 blocks. Build: ONE sibling pair (entries
// 2m, 2m+1) per thread -> short per-thread chain, 16 warps/SM for latency
// hiding. Apply: 2 points per thread (float2), coalesced staged stores.
__global__ void __launch_bounds__(512) haar_fused(const float* __restrict__ t,
                                                  const float* __restrict__ W1,
                                                  const float* __restrict__ b1,
                                                  const float* __restrict__ W2,
                                                  const float* __restrict__ b2,
                                                  const float* __restrict__ W3,
                                                  const float* __restrict__ b3,
                                                  float* __restrict__ out,
                                                  int n) {
    __shared__ float4 tab[1024];      // 16 KB LUT
    __shared__ float4 ostage[768];    // 12 KB output stage
    __shared__ u64 w3s[12];           // w3s[f*4+kk] = (W3[2kk][f], W3[2kk+1][f])

    int tid = threadIdx.x;
    int n2 = n >> 1;                              // # float2 points
    int blk2 = blockIdx.x * 512;                  // first float2 of this block
    int i2 = blk2 + tid;
    bool full_block = (blk2 + 512) <= n2;

    // ---- Prefetch this thread's 2 input points (hides behind build) ----
    const float2* t2 = reinterpret_cast<const float2*>(t);
    float2 tv2 = make_float2(0.f, 0.f);
    if (full_block) {
        tv2 = t2[i2];
    } else {
        if (i2 < n2) tv2 = t2[i2];
    }

    // ---- Stage packed W3 pairs into smem ----
    if (tid < 12) {
        int f = tid % 3, kk = tid / 3;
        w3s[f * 4 + kk] = pk2(W3[(2 * kk) * 3 + f], W3[(2 * kk + 1) * 3 + f]);
    }

    // ---- Per-thread register preloads ----
    const ulonglong2* w2v = reinterpret_cast<const ulonglong2*>(W2);
    u64 w2p[32];
#pragma unroll
    for (int r = 0; r < 16; r++) { ulonglong2 v = w2v[r]; w2p[2*r] = v.x; w2p[2*r+1] = v.y; }

    const ulonglong2* b1v = reinterpret_cast<const ulonglong2*>(b1);
    u64 b1p[4];
    { ulonglong2 v0 = b1v[0], v1 = b1v[1]; b1p[0]=v0.x; b1p[1]=v0.y; b1p[2]=v1.x; b1p[3]=v1.y; }

    const ulonglong2* b2v = reinterpret_cast<const ulonglong2*>(b2);
    u64 b2p[4];
    { ulonglong2 v0 = b2v[0], v1 = b2v[1]; b2p[0]=v0.x; b2p[1]=v0.y; b2p[2]=v1.x; b2p[3]=v1.y; }

    float b3r[3];
#pragma unroll
    for (int f = 0; f < 3; f++) b3r[f] = b3[f];

    __syncthreads();   // w3s visible

    const ulonglong2* w1v = reinterpret_cast<const ulonglong2*>(W1);

    // ---- Build: ONE sibling pair (entries 2m, 2m+1), m = tid (0..511) ----
    {
        int m = tid;

        u64 base2[4];
#pragma unroll
        for (int h = 0; h < 4; h++) base2[h] = b1p[h];

        // Levels 0..8: rows AND signs shared by the pair.
#pragma unroll
        for (int j = 0; j < 9; j++) {
            int k   = m >> (9 - j);
            int row = (1 << j) - 1 + k;
            float s = ((m >> (8 - j)) & 1) ? -1.0f : 1.0f;
            u64 s2 = pk2(s, s);
            ulonglong2 r0 = __ldg(w1v + row * 2);
            ulonglong2 r1 = __ldg(w1v + row * 2 + 1);
            base2[0] = fma2(s2, r0.x, base2[0]);
            base2[1] = fma2(s2, r0.y, base2[1]);
            base2[2] = fma2(s2, r1.x, base2[2]);
            base2[3] = fma2(s2, r1.y, base2[3]);
        }

        // Level-9 row for this pair.
        ulonglong2 f0 = __ldg(w1v + (511 + m) * 2);
        ulonglong2 f1 = __ldg(w1v + (511 + m) * 2 + 1);
        u64 fine2[4] = { f0.x, f0.y, f1.x, f1.y };

#pragma unroll
        for (int c = 0; c < 2; c++) {
            float sgn = c ? -1.0f : 1.0f;
            u64 sg2 = pk2(sgn, sgn);

            u64 bc[8];
#pragma unroll
            for (int h = 0; h < 4; h++) {
                u64 a2 = fma2(sg2, fine2[h], base2[h]);
                float lo, hi; upk2(a2, lo, hi);
                lo = fmaxf(lo, 0.0f); hi = fmaxf(hi, 0.0f);
                bc[2*h]   = pk2(lo, lo);
                bc[2*h+1] = pk2(hi, hi);
            }

            u64 h2p[4];
#pragma unroll
            for (int kk = 0; kk < 4; kk++) h2p[kk] = b2p[kk];
#pragma unroll
            for (int h = 0; h < 8; h++) {
#pragma unroll
                for (int kk = 0; kk < 4; kk++)
                    h2p[kk] = fma2(bc[h], w2p[h * 4 + kk], h2p[kk]);
            }
#pragma unroll
            for (int kk = 0; kk < 4; kk++) {
                float lo, hi; upk2(h2p[kk], lo, hi);
                h2p[kk] = pk2(fmaxf(lo, 0.0f), fmaxf(hi, 0.0f));
            }

            float o[3];
#pragma unroll
            for (int f = 0; f < 3; f++) {
                u64 acc = pk2(b3r[f], 0.0f);
#pragma unroll
                for (int kk = 0; kk < 4; kk++)
                    acc = fma2(h2p[kk], w3s[f * 4 + kk], acc);
                float lo, hi; upk2(acc, lo, hi);
                o[f] = lo + hi;
            }

            tab[2 * m + c] = make_float4(o[0], o[1], o[2], 0.0f);
        }
    }

    __syncthreads();

    // ---- Apply: 2 points per thread, staged coalesced stores ----
    float4* o4 = reinterpret_cast<float4*>(out);
    if (full_block) {
        float4 ra = tab[q_of(tv2.x)];
        float4 rb = tab[q_of(tv2.y)];

        float2* os2 = reinterpret_cast<float2*>(ostage);
        os2[3 * tid + 0] = make_float2(ra.x, ra.y);
        os2[3 * tid + 1] = make_float2(ra.z, rb.x);
        os2[3 * tid + 2] = make_float2(rb.y, rb.z);
        __syncthreads();

        // 768 float4s, coalesced: 512 threads then 256 threads.
        float4* dst = o4 + 3 * (blockIdx.x * 256);
        dst[tid] = ostage[tid];
        if (tid < 256) dst[512 + tid] = ostage[512 + tid];
    } else if (i2 < n2) {
        float4 ra = tab[q_of(tv2.x)];
        float4 rb = tab[q_of(tv2.y)];
        int p = 2 * i2;
        out[3 * p + 0] = ra.x; out[3 * p + 1] = ra.y; out[3 * p + 2] = ra.z;
        out[3 * p + 3] = rb.x; out[3 * p + 4] = rb.y; out[3 * p + 5] = rb.z;
    }

    // Odd-n tail (dead for n = 131072 but kept correct).
    if ((n & 1) && blockIdx.x == 0 && tid == 0) {
        int p = n - 1;
        float4 r = tab[q_of(t[p])];
        out[3 * p + 0] = r.x;
        out[3 * p + 1] = r.y;
        out[3 * p + 2] = r.z;
    }
}

extern "C" void kernel_launch(void* const* d_in, const int* in_sizes, int n_in,
                              void* d_out, int out_size) {
    const float* t  = (const float*)d_in[0];
    const float* W1 = (const float*)d_in[1];
    const float* b1 = (const float*)d_in[2];
    const float* W2 = (const float*)d_in[3];
    const float* b2 = (const float*)d_in[4];
    const float* W3 = (const float*)d_in[5];
    const float* b3 = (const float*)d_in[6];
    float* out = (float*)d_out;

    int n = in_sizes[0];  // B*T points

    int n2 = n >> 1;
    int threads = 512;
    int blocks = (n2 + threads - 1) / threads;
    if (blocks < 1) blocks = 1;
    haar_fused<<<blocks, threads>>>(t, W1, b1, W2, b2, W3, b3, out, n);
}